// round 3
// baseline (speedup 1.0000x reference)
#include <cuda_runtime.h>
#include <math.h>

#define T_LEN 128
#define B_DIM 128
#define I_DIM 128
#define H_DIM 512
#define W_WIN 16
#define G4H   2048   // 4*H
#define IH    640    // I+H

// ---------------- scratch (device globals; no allocation allowed) ----------
__device__ float g_h[2][B_DIM * H_DIM];
__device__ float g_c[B_DIM * H_DIM];
__device__ float g_V[W_WIN * B_DIM * H_DIM];
__device__ float g_attn[B_DIM * H_DIM];
__device__ float g_Q[B_DIM * H_DIM];

// ---------------- helpers ---------------------------------------------------
__device__ __forceinline__ unsigned smem_u32(const void* p) {
    return (unsigned)__cvta_generic_to_shared(p);
}
__device__ __forceinline__ void cp16(void* dst, const void* src) {
    asm volatile("cp.async.cg.shared.global [%0], [%1], 16;\n"
                 :: "r"(smem_u32(dst)), "l"(src));
}
__device__ __forceinline__ void cp_commit() {
    asm volatile("cp.async.commit_group;\n" ::: "memory");
}
__device__ __forceinline__ void cp_wait1() {
    asm volatile("cp.async.wait_group 1;\n" ::: "memory");
}
__device__ __forceinline__ void cp_wait0() {
    asm volatile("cp.async.wait_group 0;\n" ::: "memory");
}
// packed fp32x2: d = a*b + d   (SASS FFMA2; full fp32 precision per lane)
__device__ __forceinline__ unsigned long long pack2(float lo, float hi) {
    unsigned long long r;
    asm("mov.b64 %0, {%1, %2};" : "=l"(r) : "f"(lo), "f"(hi));
    return r;
}
__device__ __forceinline__ void ffma2(unsigned long long& d,
                                      unsigned long long a, unsigned long long b) {
    asm("fma.rn.f32x2 %0, %1, %2, %0;" : "+l"(d) : "l"(a), "l"(b));
}
__device__ __forceinline__ float2 unpack2(unsigned long long v) {
    float2 f;
    asm("mov.b64 {%0, %1}, %2;" : "=f"(f.x), "=f"(f.y) : "l"(v));
    return f;
}

// ---------------- init: h=0, c=0, V[w][b][:] = bv ---------------------------
__global__ void init_kernel(const float* __restrict__ bv) {
    int idx = blockIdx.x * blockDim.x + threadIdx.x;
    int stride = gridDim.x * blockDim.x;
    for (int i = idx; i < B_DIM * H_DIM; i += stride) {
        g_h[0][i] = 0.f;
        g_c[i] = 0.f;
    }
    for (int i = idx; i < W_WIN * B_DIM * H_DIM; i += stride) {
        g_V[i] = bv[i % H_DIM];
    }
}

// ---------------- KA: Q = [x_t|h] @ Wq + bq   AND   V[t%W] = c @ Wv + bv ----
// grid = 128 blocks x 128 threads.
// Blocks 0..63 : Q-GEMM (M=128, N=512, K=640)   tiles 32(M) x 32(N), TK=32
// Blocks 64..127: V-GEMM (M=128, N=512, K=512)
// Thread: 1 row x 4 j-pairs (8 outputs) using f32x2 packed FMA.
__global__ __launch_bounds__(128) void ka_kernel(
    int t,
    const float* __restrict__ x,
    const float* __restrict__ Wq, const float* __restrict__ bq,
    const float* __restrict__ Wv, const float* __restrict__ bv)
{
    __shared__ float As[2][32][36];   // [stage][row][k], pad 36 (align + banks)
    __shared__ float Ws[2][32][32];   // [stage][k][n]

    const int blk = blockIdx.x;
    const bool isQ = (blk < 64);
    const int bid = blk & 63;
    const int m0 = (bid >> 4) * 32;     // 4 M-tiles
    const int n0 = (bid & 15) * 32;     // 16 N-tiles

    const float* __restrict__ hin  = g_h[t & 1];
    const float* __restrict__ xt   = x + (size_t)t * B_DIM * I_DIM;
    const float* __restrict__ Wmat = isQ ? Wq : Wv;
    const int nt = isQ ? (IH / 32) : (H_DIM / 32);   // 20 or 16 k-tiles

    const int tid = threadIdx.x;
    const int tj  = tid & 3;           // pair lane: cols p*8 + tj*2 + {0,1}
    const int tr  = tid >> 2;          // 0..31 row

    // stage-load assignments (2 x cp16 each for A and W)
    auto issue = [&](int it, int s) {
        const int kk = it * 32;
        #pragma unroll
        for (int l = 0; l < 2; l++) {
            int id = tid + l * 128;
            int row = id >> 3, c4 = (id & 7) * 4;
            int gk = kk + c4;
            const float* src;
            if (isQ) {
                src = (gk < I_DIM) ? (xt + (size_t)(m0 + row) * I_DIM + gk)
                                   : (hin + (size_t)(m0 + row) * H_DIM + (gk - I_DIM));
            } else {
                src = g_c + (size_t)(m0 + row) * H_DIM + gk;
            }
            cp16(&As[s][row][c4], src);
        }
        #pragma unroll
        for (int l = 0; l < 2; l++) {
            int id = tid + l * 128;
            int k = id >> 3, c4 = (id & 7) * 4;
            cp16(&Ws[s][k][c4], Wmat + (size_t)(kk + k) * H_DIM + n0 + c4);
        }
        cp_commit();
    };

    unsigned long long acc[4] = {0ull, 0ull, 0ull, 0ull};

    issue(0, 0);
    for (int it = 0; it < nt; it++) {
        const int s = it & 1;
        if (it + 1 < nt) { issue(it + 1, s ^ 1); cp_wait1(); }
        else             { cp_wait0(); }
        __syncthreads();

        #pragma unroll 8
        for (int k = 0; k < 32; k++) {
            float a = As[s][tr][k];
            unsigned long long ap = pack2(a, a);
            #pragma unroll
            for (int p = 0; p < 4; p++) {
                unsigned long long w =
                    *(const unsigned long long*)&Ws[s][k][p * 8 + tj * 2];
                ffma2(acc[p], ap, w);
            }
        }
        __syncthreads();
    }

    const float* bias = isQ ? bq : bv;
    float* outp = isQ ? g_Q : (g_V + (size_t)(t % W_WIN) * B_DIM * H_DIM);
    const int row = m0 + tr;
    #pragma unroll
    for (int p = 0; p < 4; p++) {
        int j = n0 + p * 8 + tj * 2;
        float2 v = unpack2(acc[p]);
        float2 bb = *(const float2*)(bias + j);
        v.x += bb.x; v.y += bb.y;
        *(float2*)(outp + (size_t)row * H_DIM + j) = v;
    }
}

// ---------------- KB: scores -> softmax -> attn -----------------------------
__global__ __launch_bounds__(128) void kb_kernel(int t) {
    const float inv_sqrt_dk = 0.044194173824159216f; // 1/sqrt(512)
    int b = blockIdx.x;
    int tid = threadIdx.x;
    __shared__ float sQ[H_DIM];
    __shared__ float sS[W_WIN];
    __shared__ float sP[W_WIN];

    for (int j = tid; j < H_DIM; j += 128) sQ[j] = g_Q[(size_t)b * H_DIM + j];
    __syncthreads();

    int nv = (t + 1 < W_WIN) ? (t + 1) : W_WIN;
    int warp = tid / 32, lane = tid % 32;
    for (int w = warp; w < nv; w += 4) {
        const float* Vp = g_V + (size_t)(w * B_DIM + b) * H_DIM;
        float p = 0.f;
        for (int j = lane; j < H_DIM; j += 32) p += sQ[j] * Vp[j];
        #pragma unroll
        for (int o = 16; o > 0; o >>= 1) p += __shfl_xor_sync(0xffffffffu, p, o);
        if (lane == 0) sS[w] = p * inv_sqrt_dk;
    }
    __syncthreads();
    if (tid == 0) {
        float m = sS[0];
        for (int w = 1; w < nv; w++) m = fmaxf(m, sS[w]);
        float sum = 0.f;
        for (int w = 0; w < nv; w++) { float e = expf(sS[w] - m); sP[w] = e; sum += e; }
        float inv = 1.f / sum;
        for (int w = 0; w < nv; w++) sP[w] *= inv;
    }
    __syncthreads();
    for (int j = tid; j < H_DIM; j += 128) {
        float a = 0.f;
        for (int w = 0; w < nv; w++)
            a += sP[w] * g_V[(size_t)(w * B_DIM + b) * H_DIM + j];
        g_attn[(size_t)b * H_DIM + j] = a;
    }
}

// ---------------- KC: fused cell GEMM + LSTM pointwise ----------------------
// preact = x_t@Wi + h@Wh + attn@Wa + biases (virtual K=1152).
// grid = 256 blocks (4 M-tiles x 64 j-tiles) x 128 threads.
// Tile: BM=32 rows x 8 j-cols x 4 gates, TK=32.
// Thread: 1 row x 1 j-pair x 4 gates via f32x2 packed FMA.
__global__ __launch_bounds__(128) void kc_kernel(
    int t,
    const float* __restrict__ x,
    const float* __restrict__ Wi, const float* __restrict__ Wh,
    const float* __restrict__ Wa,
    const float* __restrict__ bi, const float* __restrict__ ba,
    float* __restrict__ out)
{
    __shared__ float As[2][32][36];   // [stage][row][k]
    __shared__ float Ws[2][32][32];   // [stage][k][g*8 + j]

    const int m0 = (blockIdx.x >> 6) * 32;  // 4 M-tiles
    const int j0 = (blockIdx.x & 63) * 8;   // 64 j-tiles

    const float* __restrict__ hin  = g_h[t & 1];
    float*       __restrict__ hout = g_h[(t + 1) & 1];
    const float* __restrict__ xt   = x + (size_t)t * B_DIM * I_DIM;

    const int tid = threadIdx.x;
    const int tj  = tid & 3;           // j-pair: cols j0 + tj*2 + {0,1}
    const int tr  = tid >> 2;          // 0..31 row

    // virtual K = 1152 : [0,128)=x/Wi  [128,640)=h/Wh  [640,1152)=attn/Wa
    auto issue = [&](int it, int s) {
        const int kk = it * 32;
        const float* Aseg; const float* Wseg; int ldA; int koff;
        if (kk < I_DIM)   { Aseg = xt;     Wseg = Wi; ldA = I_DIM; koff = kk; }
        else if (kk < IH) { Aseg = hin;    Wseg = Wh; ldA = H_DIM; koff = kk - I_DIM; }
        else              { Aseg = g_attn; Wseg = Wa; ldA = H_DIM; koff = kk - IH; }
        #pragma unroll
        for (int l = 0; l < 2; l++) {
            int id = tid + l * 128;
            int row = id >> 3, c4 = (id & 7) * 4;
            cp16(&As[s][row][c4],
                 Aseg + (size_t)(m0 + row) * ldA + koff + c4);
        }
        // W: per k, 4 gates x 2 halves of 4 floats = 8 chunks; 32k -> 256 chunks
        #pragma unroll
        for (int l = 0; l < 2; l++) {
            int id = tid + l * 128;
            int k = id >> 3;
            int rem = id & 7;
            int g = rem >> 1;
            int c4 = (rem & 1) * 4;
            cp16(&Ws[s][k][g * 8 + c4],
                 Wseg + (size_t)(koff + k) * G4H + g * H_DIM + j0 + c4);
        }
        cp_commit();
    };

    unsigned long long acc[4] = {0ull, 0ull, 0ull, 0ull}; // per gate

    const int nt = 36;  // 1152/32
    issue(0, 0);
    for (int it = 0; it < nt; it++) {
        const int s = it & 1;
        if (it + 1 < nt) { issue(it + 1, s ^ 1); cp_wait1(); }
        else             { cp_wait0(); }
        __syncthreads();

        #pragma unroll 8
        for (int k = 0; k < 32; k++) {
            float a = As[s][tr][k];
            unsigned long long ap = pack2(a, a);
            #pragma unroll
            for (int g = 0; g < 4; g++) {
                unsigned long long w =
                    *(const unsigned long long*)&Ws[s][k][g * 8 + tj * 2];
                ffma2(acc[g], ap, w);
            }
        }
        __syncthreads();
    }

    const int j = j0 + tj * 2;             // pair (j, j+1)
    const int b = m0 + tr;

    float2 pi = unpack2(acc[0]);
    float2 pf = unpack2(acc[1]);
    float2 po = unpack2(acc[2]);
    float2 pg = unpack2(acc[3]);

    float2 bi0 = *(const float2*)(bi + j);
    float2 ba0 = *(const float2*)(ba + j);
    float2 bi1 = *(const float2*)(bi + H_DIM + j);
    float2 ba1 = *(const float2*)(ba + H_DIM + j);
    float2 bi2 = *(const float2*)(bi + 2 * H_DIM + j);
    float2 ba2 = *(const float2*)(ba + 2 * H_DIM + j);
    float2 bi3 = *(const float2*)(bi + 3 * H_DIM + j);
    float2 ba3 = *(const float2*)(ba + 3 * H_DIM + j);

    pi.x += bi0.x + ba0.x;  pi.y += bi0.y + ba0.y;
    pf.x += bi1.x + ba1.x;  pf.y += bi1.y + ba1.y;
    po.x += bi2.x + ba2.x;  po.y += bi2.y + ba2.y;
    pg.x += bi3.x + ba3.x;  pg.y += bi3.y + ba3.y;

    size_t idx = (size_t)b * H_DIM + j;
    float2 cold = *(const float2*)(g_c + idx);

    float igx = 1.f / (1.f + expf(-pi.x)), igy = 1.f / (1.f + expf(-pi.y));
    float fgx = 1.f / (1.f + expf(-pf.x)), fgy = 1.f / (1.f + expf(-pf.y));
    float ogx = 1.f / (1.f + expf(-po.x)), ogy = 1.f / (1.f + expf(-po.y));
    float ggx = tanhf(pg.x),               ggy = tanhf(pg.y);

    float2 cn, hn;
    cn.x = cold.x * fgx + igx * ggx;
    cn.y = cold.y * fgy + igy * ggy;
    hn.x = ogx * tanhf(cn.x);
    hn.y = ogy * tanhf(cn.y);

    *(float2*)(g_c + idx) = cn;
    *(float2*)(hout + idx) = hn;
    *(float2*)(out + (size_t)t * B_DIM * H_DIM + idx) = hn;
}

// ---------------- launcher --------------------------------------------------
extern "C" void kernel_launch(void* const* d_in, const int* in_sizes, int n_in,
                              void* d_out, int out_size) {
    const float* x  = (const float*)d_in[0];
    const float* Wi = (const float*)d_in[1];
    const float* bi = (const float*)d_in[2];
    const float* Wh = (const float*)d_in[3];
    const float* Wv = (const float*)d_in[4];
    const float* bv = (const float*)d_in[5];
    const float* Wq = (const float*)d_in[6];
    const float* bq = (const float*)d_in[7];
    const float* Wa = (const float*)d_in[8];
    const float* ba = (const float*)d_in[9];
    float* out = (float*)d_out;

    init_kernel<<<1024, 256>>>(bv);
    for (int t = 0; t < T_LEN; t++) {
        ka_kernel<<<128, 128>>>(t, x, Wq, bq, Wv, bv);
        kb_kernel<<<128, 128>>>(t);
        kc_kernel<<<256, 128>>>(t, x, Wi, Wh, Wa, bi, ba, out);
    }
}

// round 4
// speedup vs baseline: 1.3866x; 1.3866x over previous
#include <cuda_runtime.h>
#include <math.h>

#define T_LEN 128
#define B_DIM 128
#define I_DIM 128
#define H_DIM 512
#define W_WIN 16
#define G4H   2048   // 4*H
#define IH    640    // I+H

// ---------------- scratch (device globals; no allocation allowed) ----------
__device__ float g_h[2][B_DIM * H_DIM];
__device__ float g_c[B_DIM * H_DIM];
__device__ float g_V[W_WIN * B_DIM * H_DIM];
__device__ float g_attn[B_DIM * H_DIM];
__device__ float g_Q[B_DIM * H_DIM];

// ---------------- helpers ---------------------------------------------------
__device__ __forceinline__ unsigned smem_u32(const void* p) {
    return (unsigned)__cvta_generic_to_shared(p);
}
__device__ __forceinline__ void cp16(void* dst, const void* src) {
    asm volatile("cp.async.cg.shared.global [%0], [%1], 16;\n"
                 :: "r"(smem_u32(dst)), "l"(src));
}
__device__ __forceinline__ void cp_commit() {
    asm volatile("cp.async.commit_group;\n" ::: "memory");
}
__device__ __forceinline__ void cp_wait1() {
    asm volatile("cp.async.wait_group 1;\n" ::: "memory");
}
__device__ __forceinline__ void cp_wait0() {
    asm volatile("cp.async.wait_group 0;\n" ::: "memory");
}

// ---------------- init: h=0, c=0, V[w][b][:] = bv ---------------------------
__global__ void init_kernel(const float* __restrict__ bv) {
    int idx = blockIdx.x * blockDim.x + threadIdx.x;
    int stride = gridDim.x * blockDim.x;
    for (int i = idx; i < B_DIM * H_DIM; i += stride) {
        g_h[0][i] = 0.f;
        g_c[i] = 0.f;
    }
    for (int i = idx; i < W_WIN * B_DIM * H_DIM; i += stride) {
        g_V[i] = bv[i % H_DIM];
    }
}

// ---------------- KA: Q = [x_t|h] @ Wq + bq   AND   V[t%W] = c @ Wv + bv ----
// grid = 128 blocks x 128 threads.
// Blocks 0..63 : Q-GEMM (M=128, N=512, K=640)  tiles 32(M) x 32(N), TK=32
// Blocks 64..127: V-GEMM (M=128, N=512, K=512)
// A transposed to smem [k][row]; thread = 2 rows x 4 contiguous cols.
__global__ __launch_bounds__(128) void ka_kernel(
    int t,
    const float* __restrict__ x,
    const float* __restrict__ Wq, const float* __restrict__ bq,
    const float* __restrict__ Wv, const float* __restrict__ bv)
{
    __shared__ float As[2][32][36];   // [stage][k][row], stride 36 (16B-aligned)
    __shared__ float Ws[2][32][32];   // [stage][k][n]

    const int blk = blockIdx.x;
    const bool isQ = (blk < 64);
    const int bid = blk & 63;
    const int m0 = (bid >> 4) * 32;     // 4 M-tiles
    const int n0 = (bid & 15) * 32;     // 16 N-tiles

    const float* __restrict__ hin  = g_h[t & 1];
    const float* __restrict__ xt   = x + (size_t)t * B_DIM * I_DIM;
    const float* __restrict__ Wmat = isQ ? Wq : Wv;
    const int nt = isQ ? (IH / 32) : (H_DIM / 32);   // 20 or 16 k-tiles

    const int tid = threadIdx.x;
    const int tj  = tid & 7;           // cols n0 + tj*4 .. +3
    const int rg  = tid >> 3;          // 0..15 -> rows rg*2, rg*2+1

    // A staging: thread owns row=tid>>2, k-span (tid&3)*8 .. +7
    const int arow = tid >> 2;
    const int ak0  = (tid & 3) * 8;

    float ar[8];

    auto ldgA = [&](int it) {
        const int kk = it * 32;
        const float* p;
        if (isQ) {
            int gk = kk + ak0;
            p = (gk < I_DIM) ? (xt + (size_t)(m0 + arow) * I_DIM + gk)
                             : (hin + (size_t)(m0 + arow) * H_DIM + (gk - I_DIM));
        } else {
            p = g_c + (size_t)(m0 + arow) * H_DIM + kk + ak0;
        }
        *(float4*)&ar[0] = *(const float4*)p;
        *(float4*)&ar[4] = *(const float4*)(p + 4);
    };
    auto stsA = [&](int s) {
        #pragma unroll
        for (int i = 0; i < 8; i++) As[s][ak0 + i][arow] = ar[i];
    };
    auto cpW = [&](int it, int s) {
        const int kk = it * 32;
        #pragma unroll
        for (int l = 0; l < 2; l++) {
            int id = tid + l * 128;
            int k = id >> 3, c4 = (id & 7) * 4;
            cp16(&Ws[s][k][c4], Wmat + (size_t)(kk + k) * H_DIM + n0 + c4);
        }
        cp_commit();
    };

    float acc[2][4] = {};

    ldgA(0); cpW(0, 0);
    for (int it = 0; it < nt; it++) {
        const int s = it & 1;
        stsA(s);
        if (it + 1 < nt) { ldgA(it + 1); cpW(it + 1, s ^ 1); cp_wait1(); }
        else             { cp_wait0(); }
        __syncthreads();

        #pragma unroll 8
        for (int k = 0; k < 32; k++) {
            float2 a = *(const float2*)&As[s][k][rg * 2];
            float4 w = *(const float4*)&Ws[s][k][tj * 4];
            acc[0][0] += a.x * w.x;  acc[0][1] += a.x * w.y;
            acc[0][2] += a.x * w.z;  acc[0][3] += a.x * w.w;
            acc[1][0] += a.y * w.x;  acc[1][1] += a.y * w.y;
            acc[1][2] += a.y * w.z;  acc[1][3] += a.y * w.w;
        }
        __syncthreads();
    }

    const float* bias = isQ ? bq : bv;
    float* outp = isQ ? g_Q : (g_V + (size_t)(t % W_WIN) * B_DIM * H_DIM);
    float4 bb = *(const float4*)(bias + n0 + tj * 4);
    #pragma unroll
    for (int r = 0; r < 2; r++) {
        int row = m0 + rg * 2 + r;
        float4 o;
        o.x = acc[r][0] + bb.x;  o.y = acc[r][1] + bb.y;
        o.z = acc[r][2] + bb.z;  o.w = acc[r][3] + bb.w;
        *(float4*)(outp + (size_t)row * H_DIM + n0 + tj * 4) = o;
    }
}

// ---------------- KB: scores -> softmax -> attn -----------------------------
__global__ __launch_bounds__(128) void kb_kernel(int t) {
    const float inv_sqrt_dk = 0.044194173824159216f; // 1/sqrt(512)
    int b = blockIdx.x;
    int tid = threadIdx.x;
    __shared__ float sQ[H_DIM];
    __shared__ float sS[W_WIN];
    __shared__ float sP[W_WIN];

    for (int j = tid; j < H_DIM; j += 128) sQ[j] = g_Q[(size_t)b * H_DIM + j];
    __syncthreads();

    int nv = (t + 1 < W_WIN) ? (t + 1) : W_WIN;
    int warp = tid / 32, lane = tid % 32;
    for (int w = warp; w < nv; w += 4) {
        const float* Vp = g_V + (size_t)(w * B_DIM + b) * H_DIM;
        float p = 0.f;
        for (int j = lane; j < H_DIM; j += 32) p += sQ[j] * Vp[j];
        #pragma unroll
        for (int o = 16; o > 0; o >>= 1) p += __shfl_xor_sync(0xffffffffu, p, o);
        if (lane == 0) sS[w] = p * inv_sqrt_dk;
    }
    __syncthreads();
    if (tid == 0) {
        float m = sS[0];
        for (int w = 1; w < nv; w++) m = fmaxf(m, sS[w]);
        float sum = 0.f;
        for (int w = 0; w < nv; w++) { float e = expf(sS[w] - m); sP[w] = e; sum += e; }
        float inv = 1.f / sum;
        for (int w = 0; w < nv; w++) sP[w] *= inv;
    }
    __syncthreads();
    for (int j = tid; j < H_DIM; j += 128) {
        float a = 0.f;
        for (int w = 0; w < nv; w++)
            a += sP[w] * g_V[(size_t)(w * B_DIM + b) * H_DIM + j];
        g_attn[(size_t)b * H_DIM + j] = a;
    }
}

// ---------------- KC: fused cell GEMM + LSTM pointwise ----------------------
// preact = x_t@Wi + h@Wh + attn@Wa + biases (virtual K=1152).
// grid = 128 blocks (4 M-tiles x 32 j-tiles) x 128 threads.
// Tile: BM=32 rows x 16 j x 4 gates, TK=32.
// A transposed to smem [k][row]; thread = 4 rows x 4 gates x 1 j.
__global__ __launch_bounds__(128) void kc_kernel(
    int t,
    const float* __restrict__ x,
    const float* __restrict__ Wi, const float* __restrict__ Wh,
    const float* __restrict__ Wa,
    const float* __restrict__ bi, const float* __restrict__ ba,
    float* __restrict__ out)
{
    __shared__ float As[2][32][36];   // [stage][k][row]
    __shared__ float Ws[2][32][64];   // [stage][k][g*16 + j]

    const int m0 = (blockIdx.x >> 5) * 32;  // 4 M-tiles
    const int j0 = (blockIdx.x & 31) * 16;  // 32 j-tiles

    const float* __restrict__ hin  = g_h[t & 1];
    float*       __restrict__ hout = g_h[(t + 1) & 1];
    const float* __restrict__ xt   = x + (size_t)t * B_DIM * I_DIM;

    const int tid = threadIdx.x;
    const int tj  = tid & 15;          // j within tile
    const int rg  = tid >> 4;          // 0..7 -> rows rg*4 .. rg*4+3

    const int arow = tid >> 2;
    const int ak0  = (tid & 3) * 8;

    float ar[8];

    // virtual K = 1152 : [0,128)=x/Wi  [128,640)=h/Wh  [640,1152)=attn/Wa
    auto ldgA = [&](int it) {
        const int kk = it * 32;
        const float* Aseg; int ldA, koff;
        if (kk < I_DIM)   { Aseg = xt;     ldA = I_DIM; koff = kk; }
        else if (kk < IH) { Aseg = hin;    ldA = H_DIM; koff = kk - I_DIM; }
        else              { Aseg = g_attn; ldA = H_DIM; koff = kk - IH; }
        const float* p = Aseg + (size_t)(m0 + arow) * ldA + koff + ak0;
        *(float4*)&ar[0] = *(const float4*)p;
        *(float4*)&ar[4] = *(const float4*)(p + 4);
    };
    auto stsA = [&](int s) {
        #pragma unroll
        for (int i = 0; i < 8; i++) As[s][ak0 + i][arow] = ar[i];
    };
    auto cpW = [&](int it, int s) {
        const int kk = it * 32;
        const float* Wseg; int koff;
        if (kk < I_DIM)   { Wseg = Wi; koff = kk; }
        else if (kk < IH) { Wseg = Wh; koff = kk - I_DIM; }
        else              { Wseg = Wa; koff = kk - IH; }
        #pragma unroll
        for (int l = 0; l < 4; l++) {
            int id = tid + l * 128;
            int k = id >> 4;
            int ch = id & 15;
            int g = ch >> 2, c4 = (ch & 3) * 4;
            cp16(&Ws[s][k][g * 16 + c4],
                 Wseg + (size_t)(koff + k) * G4H + g * H_DIM + j0 + c4);
        }
        cp_commit();
    };

    float acc[4][4] = {};  // [row][gate]

    const int nt = 36;     // 1152/32
    ldgA(0); cpW(0, 0);
    for (int it = 0; it < nt; it++) {
        const int s = it & 1;
        stsA(s);
        if (it + 1 < nt) { ldgA(it + 1); cpW(it + 1, s ^ 1); cp_wait1(); }
        else             { cp_wait0(); }
        __syncthreads();

        #pragma unroll 8
        for (int k = 0; k < 32; k++) {
            float4 a = *(const float4*)&As[s][k][rg * 4];
            #pragma unroll
            for (int g = 0; g < 4; g++) {
                float w = Ws[s][k][g * 16 + tj];
                acc[0][g] += a.x * w;
                acc[1][g] += a.y * w;
                acc[2][g] += a.z * w;
                acc[3][g] += a.w * w;
            }
        }
        __syncthreads();
    }

    const int j = j0 + tj;
    const float bias_i = bi[j]             + ba[j];
    const float bias_f = bi[H_DIM + j]     + ba[H_DIM + j];
    const float bias_o = bi[2 * H_DIM + j] + ba[2 * H_DIM + j];
    const float bias_g = bi[3 * H_DIM + j] + ba[3 * H_DIM + j];

    #pragma unroll
    for (int r = 0; r < 4; r++) {
        int b = m0 + rg * 4 + r;
        float pi = acc[r][0] + bias_i;
        float pf = acc[r][1] + bias_f;
        float po = acc[r][2] + bias_o;
        float pg = acc[r][3] + bias_g;
        float ig = 1.f / (1.f + expf(-pi));
        float fg = 1.f / (1.f + expf(-pf));
        float og = 1.f / (1.f + expf(-po));
        float gg = tanhf(pg);
        size_t idx = (size_t)b * H_DIM + j;
        float cn = g_c[idx] * fg + ig * gg;
        float hn = og * tanhf(cn);
        g_c[idx] = cn;
        hout[idx] = hn;
        out[(size_t)t * B_DIM * H_DIM + idx] = hn;
    }
}

// ---------------- launcher --------------------------------------------------
extern "C" void kernel_launch(void* const* d_in, const int* in_sizes, int n_in,
                              void* d_out, int out_size) {
    const float* x  = (const float*)d_in[0];
    const float* Wi = (const float*)d_in[1];
    const float* bi = (const float*)d_in[2];
    const float* Wh = (const float*)d_in[3];
    const float* Wv = (const float*)d_in[4];
    const float* bv = (const float*)d_in[5];
    const float* Wq = (const float*)d_in[6];
    const float* bq = (const float*)d_in[7];
    const float* Wa = (const float*)d_in[8];
    const float* ba = (const float*)d_in[9];
    float* out = (float*)d_out;

    init_kernel<<<1024, 256>>>(bv);
    for (int t = 0; t < T_LEN; t++) {
        ka_kernel<<<128, 128>>>(t, x, Wq, bq, Wv, bv);
        kb_kernel<<<128, 128>>>(t);
        kc_kernel<<<128, 128>>>(t, x, Wi, Wh, Wa, bi, ba, out);
    }
}